// round 4
// baseline (speedup 1.0000x reference)
#include <cuda_runtime.h>
#include <math.h>

#define IN_CH 128
#define HID 64
#define NMAX 50000
#define EMAX 800000

// Scratch (__device__ globals; no allocation allowed)
__device__ float g_deg[NMAX];              // degree, then dinv in place
__device__ float g_h[NMAX * HID];          // h' = (X@W) * dinv[row]  (gather source)
__device__ float g_agg1[NMAX * HID];       // layer-1 aggregation (init = h' via dual-store)
__device__ float g_agg2[NMAX * HID];       // layer-2 aggregation

// ---------------------------------------------------------------------------
__global__ void init_deg_kernel(int n) {
    int i = blockIdx.x * blockDim.x + threadIdx.x;
    if (i < n) g_deg[i] = 1.0f;            // self-loop contributes 1
}

__global__ void degree_kernel(const int* __restrict__ dst, int e) {
    int i = blockIdx.x * blockDim.x + threadIdx.x;
    if (i < e) {
        float* p = &g_deg[__ldg(dst + i)];
        asm volatile("red.global.add.f32 [%0], %1;" :: "l"(p), "f"(1.0f) : "memory");
    }
}

__global__ void dinv_kernel(int n) {
    int i = blockIdx.x * blockDim.x + threadIdx.x;
    if (i < n) g_deg[i] = rsqrtf(g_deg[i]);
}

// ---------------------------------------------------------------------------
// GEMM: out[i][c] = dinv[i] * sum_k in[i][k] * W[k][c], dual-stored to H and AGG.
// TRANS: input transform z = relu(dinv[i]*in[i][k] + bIn[k])  (layer-2 input path)
// Block: 256 threads -> 64 nodes x 64 cols, 3 CTAs/SM.
// Thread (tx,ty): cols tx*8..+8, nodes ty and ty+32. X tile stored transposed
// Xs[k][node] with odd pitch (bank-conflict-free fill and read).
template <int K, bool TRANS>
__global__ void __launch_bounds__(256, 3)
gemm_kernel(const float* __restrict__ X, const float* __restrict__ W,
            const float* __restrict__ bIn,
            float* __restrict__ H, float* __restrict__ AGG, int n) {
    constexpr int XT = 64 + 1;             // transposed-tile pitch (odd => no conflicts)
    __shared__ float Ws[K * HID];
    __shared__ float Xs[K * XT];
    const int t = threadIdx.x;
    const int node0 = blockIdx.x * 64;

    // load W [K,HID] coalesced (float4)
    for (int i = t * 4; i < K * HID; i += 1024)
        *(float4*)(Ws + i) = *(const float4*)(W + i);

    // load X tile transposed: Xs[c][r] = X[node0+r][c]; scalar, coalesced in c
    for (int i = t; i < 64 * K; i += 256) {
        int r = i / K, c = i % K;
        int node = node0 + r;
        float v = 0.f;
        if (node < n) {
            v = __ldg(X + node * K + c);
            if (TRANS) v = fmaxf(fmaf(g_deg[node], v, __ldg(bIn + c)), 0.f);
        }
        Xs[c * XT + r] = v;
    }
    __syncthreads();

    const int tx = t & 7;                  // col group
    const int ty = t >> 3;                 // node 0..31 (and +32)
    const int c0 = tx * 8;

    unsigned long long acc[2][4];          // [node m][col pair] f32x2 accumulators
#pragma unroll
    for (int m = 0; m < 2; ++m)
#pragma unroll
        for (int j = 0; j < 4; ++j) acc[m][j] = 0ULL;

#pragma unroll 8
    for (int k = 0; k < K; ++k) {
        ulonglong2 wA = *(const ulonglong2*)(Ws + k * HID + c0);
        ulonglong2 wB = *(const ulonglong2*)(Ws + k * HID + c0 + 4);
        float x0 = Xs[k * XT + ty];
        float x1 = Xs[k * XT + 32 + ty];
        unsigned long long xx0, xx1;
        asm("mov.b64 %0, {%1, %1};" : "=l"(xx0) : "f"(x0));
        asm("mov.b64 %0, {%1, %1};" : "=l"(xx1) : "f"(x1));
        asm("fma.rn.f32x2 %0, %1, %2, %0;" : "+l"(acc[0][0]) : "l"(wA.x), "l"(xx0));
        asm("fma.rn.f32x2 %0, %1, %2, %0;" : "+l"(acc[0][1]) : "l"(wA.y), "l"(xx0));
        asm("fma.rn.f32x2 %0, %1, %2, %0;" : "+l"(acc[0][2]) : "l"(wB.x), "l"(xx0));
        asm("fma.rn.f32x2 %0, %1, %2, %0;" : "+l"(acc[0][3]) : "l"(wB.y), "l"(xx0));
        asm("fma.rn.f32x2 %0, %1, %2, %0;" : "+l"(acc[1][0]) : "l"(wA.x), "l"(xx1));
        asm("fma.rn.f32x2 %0, %1, %2, %0;" : "+l"(acc[1][1]) : "l"(wA.y), "l"(xx1));
        asm("fma.rn.f32x2 %0, %1, %2, %0;" : "+l"(acc[1][2]) : "l"(wB.x), "l"(xx1));
        asm("fma.rn.f32x2 %0, %1, %2, %0;" : "+l"(acc[1][3]) : "l"(wB.y), "l"(xx1));
    }

#pragma unroll
    for (int m = 0; m < 2; ++m) {
        int node = node0 + ty + 32 * m;
        if (node < n) {
            float di = g_deg[node];
            float o[8];
            asm("mov.b64 {%0,%1}, %2;" : "=f"(o[0]), "=f"(o[1]) : "l"(acc[m][0]));
            asm("mov.b64 {%0,%1}, %2;" : "=f"(o[2]), "=f"(o[3]) : "l"(acc[m][1]));
            asm("mov.b64 {%0,%1}, %2;" : "=f"(o[4]), "=f"(o[5]) : "l"(acc[m][2]));
            asm("mov.b64 {%0,%1}, %2;" : "=f"(o[6]), "=f"(o[7]) : "l"(acc[m][3]));
            float4 r0 = make_float4(o[0] * di, o[1] * di, o[2] * di, o[3] * di);
            float4 r1 = make_float4(o[4] * di, o[5] * di, o[6] * di, o[7] * di);
            int off = node * HID + c0;
            *(float4*)(H + off) = r0;
            *(float4*)(H + off + 4) = r1;
            *(float4*)(AGG + off) = r0;    // self-loop init: agg starts at h'[node]
            *(float4*)(AGG + off + 4) = r1;
        }
    }
}

// ---------------------------------------------------------------------------
// aggregation: agg[dst] += h'[src]  (unweighted; norm folded into producer/consumer)
// 16 lanes per edge, one red.global.add.v4.f32 per lane.
__global__ void agg_kernel(const int* __restrict__ src, const int* __restrict__ dst,
                           const float* __restrict__ h, float* __restrict__ agg, int e) {
    int tid = blockIdx.x * blockDim.x + threadIdx.x;
    int edge = tid >> 4;
    int q = tid & 15;
    if (edge >= e) return;
    int s = __ldg(src + edge);
    int d = __ldg(dst + edge);
    float4 v = *(const float4*)(h + s * HID + q * 4);
    float* p = agg + d * HID + q * 4;
    asm volatile("red.global.add.v4.f32 [%0], {%1,%2,%3,%4};"
                 :: "l"(p), "f"(v.x), "f"(v.y), "f"(v.z), "f"(v.w) : "memory");
}

// ---------------------------------------------------------------------------
// decode: out[e] = dot(z[src], z[dst]), z = dinv*agg2 + b2 applied on the fly.
// 16 lanes per edge, float4 per lane, shfl-xor reduce within the 16-lane group.
__global__ void decode_kernel(const int* __restrict__ src, const int* __restrict__ dst,
                              const float* __restrict__ agg, const float* __restrict__ b,
                              float* __restrict__ out, int e) {
    int tid = blockIdx.x * blockDim.x + threadIdx.x;
    int edge = tid >> 4;
    int q = tid & 15;
    if (edge >= e) return;
    int s = __ldg(src + edge);
    int d = __ldg(dst + edge);
    float ds = g_deg[s], dd = g_deg[d];
    float4 as = *(const float4*)(agg + s * HID + q * 4);
    float4 ad = *(const float4*)(agg + d * HID + q * 4);
    float4 bb = *(const float4*)(b + q * 4);
    float p;
    {
        float zs = fmaf(ds, as.x, bb.x), zd = fmaf(dd, ad.x, bb.x);
        p = zs * zd;
        zs = fmaf(ds, as.y, bb.y); zd = fmaf(dd, ad.y, bb.y); p = fmaf(zs, zd, p);
        zs = fmaf(ds, as.z, bb.z); zd = fmaf(dd, ad.z, bb.z); p = fmaf(zs, zd, p);
        zs = fmaf(ds, as.w, bb.w); zd = fmaf(dd, ad.w, bb.w); p = fmaf(zs, zd, p);
    }
    p += __shfl_xor_sync(0xffffffffu, p, 8);
    p += __shfl_xor_sync(0xffffffffu, p, 4);
    p += __shfl_xor_sync(0xffffffffu, p, 2);
    p += __shfl_xor_sync(0xffffffffu, p, 1);
    if (q == 0) out[edge] = p;
}

// ---------------------------------------------------------------------------
extern "C" void kernel_launch(void* const* d_in, const int* in_sizes, int n_in,
                              void* d_out, int out_size) {
    const float* x  = (const float*)d_in[0];   // [n, IN_CH]
    const int*   ei = (const int*)d_in[1];     // [2, e]
    const float* W1 = (const float*)d_in[2];
    const float* b1 = (const float*)d_in[3];
    const float* W2 = (const float*)d_in[4];
    const float* b2 = (const float*)d_in[5];
    float* out = (float*)d_out;                // [e]

    int n = in_sizes[0] / IN_CH;
    int e = in_sizes[1] / 2;
    const int* src = ei;
    const int* dst = ei + e;

    float *p_h, *p_agg1, *p_agg2;
    cudaGetSymbolAddress((void**)&p_h, g_h);
    cudaGetSymbolAddress((void**)&p_agg1, g_agg1);
    cudaGetSymbolAddress((void**)&p_agg2, g_agg2);

    const int T = 256;
    int eg = (e * 16 + T - 1) / T;             // 16 lanes per edge

    init_deg_kernel<<<(n + T - 1) / T, T>>>(n);
    degree_kernel<<<(e + T - 1) / T, T>>>(dst, e);
    dinv_kernel<<<(n + T - 1) / T, T>>>(n);

    // layer 1: h' = (X@W1)*dinv, dual-store (agg1 starts at self-loop term)
    gemm_kernel<IN_CH, false><<<(n + 63) / 64, T>>>(x, W1, nullptr, p_h, p_agg1, n);
    agg_kernel<<<eg, T>>>(src, dst, p_h, p_agg1, e);

    // layer 2: input z1 = relu(dinv*agg1 + b1) fused into GEMM load
    gemm_kernel<HID, true><<<(n + 63) / 64, T>>>(p_agg1, W2, b1, p_h, p_agg2, n);
    agg_kernel<<<eg, T>>>(src, dst, p_h, p_agg2, e);

    // decode with z2 = dinv*agg2 + b2 fused
    decode_kernel<<<eg, T>>>(src, dst, p_agg2, b2, out, e);
}

// round 5
// speedup vs baseline: 1.2941x; 1.2941x over previous
#include <cuda_runtime.h>
#include <math.h>

#define IN_CH 128
#define HID 64
#define NMAX 50000
#define EMAX 800000

// Scratch (__device__ globals; no allocation allowed)
__device__ float g_deg[NMAX];              // degree, then dinv in place
__device__ float g_h[NMAX * HID];          // h' = (X@W) * dinv[row]  (gather source)
__device__ float g_agg1[NMAX * HID];       // layer-1 aggregation (init = h' via dual-store)
__device__ float g_agg2[NMAX * HID];       // layer-2 aggregation

// ---------------------------------------------------------------------------
__global__ void init_deg_kernel(int n) {
    int i = blockIdx.x * blockDim.x + threadIdx.x;
    if (i < n) g_deg[i] = 1.0f;            // self-loop contributes 1
}

__global__ void degree_kernel(const int* __restrict__ dst, int e) {
    int i = blockIdx.x * blockDim.x + threadIdx.x;
    if (i < e) {
        float* p = &g_deg[__ldg(dst + i)];
        asm volatile("red.global.add.f32 [%0], %1;" :: "l"(p), "f"(1.0f) : "memory");
    }
}

__global__ void dinv_kernel(int n) {
    int i = blockIdx.x * blockDim.x + threadIdx.x;
    if (i < n) g_deg[i] = rsqrtf(g_deg[i]);
}

// ---------------------------------------------------------------------------
// GEMM: out[i][c] = dinv[i] * sum_k in[i][k] * W[k][c], dual-stored to H and AGG.
// TRANS: input transform z = relu(dinv[i]*in[i][k] + bIn[k])  (layer-2 input path)
// 128 threads -> 128 nodes x 64 cols. Thread (tx,ty): cols {4tx..+4, 4tx+32..+4},
// nodes 8*ty..+8. X tile stored TRANSPOSED Xs[k][node] (pitch 128):
//  - fill: thread t streams row node0+t via LDG.128, 4 consecutive-lane STS (no conflicts)
//  - read: float4 at (k,8ty): 4 distinct 32B-spaced addrs/warp, conflict-free
// 32 f32x2 accumulators per thread; per k per warp: 4 LDS.128 + 32 FFMA2 -> fma-bound.
template <int K, bool TRANS>
__global__ void __launch_bounds__(128, 2)
gemm_kernel(const float* __restrict__ X, const float* __restrict__ W,
            const float* __restrict__ bIn,
            float* __restrict__ H, float* __restrict__ AGG, int n) {
    __shared__ float Ws[K * HID];
    __shared__ float Xs[K * 128];          // [k][node]
    const int t = threadIdx.x;
    const int node0 = blockIdx.x * 128;

    // load W [K,HID] coalesced (float4)
    for (int i = t * 4; i < K * HID; i += 512)
        *(float4*)(Ws + i) = *(const float4*)(W + i);

    // fill X transposed: thread t streams its node row
    {
        int node = node0 + t;
        bool ok = node < n;
        float di = (TRANS && ok) ? g_deg[node] : 0.f;
#pragma unroll 4
        for (int g = 0; g < K / 4; ++g) {
            float4 v = make_float4(0.f, 0.f, 0.f, 0.f);
            if (ok) {
                v = *(const float4*)(X + node * K + g * 4);
                if (TRANS) {
                    float4 b = *(const float4*)(bIn + g * 4);
                    v.x = fmaxf(fmaf(di, v.x, b.x), 0.f);
                    v.y = fmaxf(fmaf(di, v.y, b.y), 0.f);
                    v.z = fmaxf(fmaf(di, v.z, b.z), 0.f);
                    v.w = fmaxf(fmaf(di, v.w, b.w), 0.f);
                }
            }
            Xs[(4 * g + 0) * 128 + t] = v.x;
            Xs[(4 * g + 1) * 128 + t] = v.y;
            Xs[(4 * g + 2) * 128 + t] = v.z;
            Xs[(4 * g + 3) * 128 + t] = v.w;
        }
    }
    __syncthreads();

    const int tx = t & 7;                  // col group
    const int ty = t >> 3;                 // node octet 0..15
    const int cA = tx * 4;                 // cols cA..cA+3 and cA+32..cA+35
    const int n0 = ty * 8;

    unsigned long long acc[8][4];          // [node j][col pair] f32x2
#pragma unroll
    for (int j = 0; j < 8; ++j)
#pragma unroll
        for (int p = 0; p < 4; ++p) acc[j][p] = 0ULL;

#pragma unroll 2
    for (int k = 0; k < K; ++k) {
        ulonglong2 wA = *(const ulonglong2*)(Ws + k * HID + cA);        // cols cA..+3
        ulonglong2 wB = *(const ulonglong2*)(Ws + k * HID + cA + 32);   // cols cA+32..+3
        float4 xa = *(const float4*)(Xs + k * 128 + n0);
        float4 xb = *(const float4*)(Xs + k * 128 + n0 + 4);
        float xs[8] = {xa.x, xa.y, xa.z, xa.w, xb.x, xb.y, xb.z, xb.w};
#pragma unroll
        for (int j = 0; j < 8; ++j) {
            unsigned long long xx;
            asm("mov.b64 %0, {%1, %1};" : "=l"(xx) : "f"(xs[j]));
            asm("fma.rn.f32x2 %0, %1, %2, %0;" : "+l"(acc[j][0]) : "l"(wA.x), "l"(xx));
            asm("fma.rn.f32x2 %0, %1, %2, %0;" : "+l"(acc[j][1]) : "l"(wA.y), "l"(xx));
            asm("fma.rn.f32x2 %0, %1, %2, %0;" : "+l"(acc[j][2]) : "l"(wB.x), "l"(xx));
            asm("fma.rn.f32x2 %0, %1, %2, %0;" : "+l"(acc[j][3]) : "l"(wB.y), "l"(xx));
        }
    }

#pragma unroll
    for (int j = 0; j < 8; ++j) {
        int node = node0 + n0 + j;
        if (node < n) {
            float di = g_deg[node];
            float o[8];
            asm("mov.b64 {%0,%1}, %2;" : "=f"(o[0]), "=f"(o[1]) : "l"(acc[j][0]));
            asm("mov.b64 {%0,%1}, %2;" : "=f"(o[2]), "=f"(o[3]) : "l"(acc[j][1]));
            asm("mov.b64 {%0,%1}, %2;" : "=f"(o[4]), "=f"(o[5]) : "l"(acc[j][2]));
            asm("mov.b64 {%0,%1}, %2;" : "=f"(o[6]), "=f"(o[7]) : "l"(acc[j][3]));
            float4 r0 = make_float4(o[0] * di, o[1] * di, o[2] * di, o[3] * di);
            float4 r1 = make_float4(o[4] * di, o[5] * di, o[6] * di, o[7] * di);
            int off = node * HID + cA;
            *(float4*)(H + off) = r0;
            *(float4*)(H + off + 32) = r1;
            *(float4*)(AGG + off) = r0;    // self-loop init: agg starts at h'[node]
            *(float4*)(AGG + off + 32) = r1;
        }
    }
}

// ---------------------------------------------------------------------------
// aggregation: agg[dst] += h'[src]  (unweighted; norm folded into producer/consumer)
// 16 lanes per edge, one red.global.add.v4.f32 per lane.
__global__ void agg_kernel(const int* __restrict__ src, const int* __restrict__ dst,
                           const float* __restrict__ h, float* __restrict__ agg, int e) {
    int tid = blockIdx.x * blockDim.x + threadIdx.x;
    int edge = tid >> 4;
    int q = tid & 15;
    if (edge >= e) return;
    int s = __ldg(src + edge);
    int d = __ldg(dst + edge);
    float4 v = *(const float4*)(h + s * HID + q * 4);
    float* p = agg + d * HID + q * 4;
    asm volatile("red.global.add.v4.f32 [%0], {%1,%2,%3,%4};"
                 :: "l"(p), "f"(v.x), "f"(v.y), "f"(v.z), "f"(v.w) : "memory");
}

// ---------------------------------------------------------------------------
// decode: out[e] = dot(z[src], z[dst]), z = dinv*agg2 + b2 applied on the fly.
// 16 lanes per edge, float4 per lane, shfl-xor reduce within the 16-lane group.
__global__ void decode_kernel(const int* __restrict__ src, const int* __restrict__ dst,
                              const float* __restrict__ agg, const float* __restrict__ b,
                              float* __restrict__ out, int e) {
    int tid = blockIdx.x * blockDim.x + threadIdx.x;
    int edge = tid >> 4;
    int q = tid & 15;
    if (edge >= e) return;
    int s = __ldg(src + edge);
    int d = __ldg(dst + edge);
    float ds = g_deg[s], dd = g_deg[d];
    float4 as = *(const float4*)(agg + s * HID + q * 4);
    float4 ad = *(const float4*)(agg + d * HID + q * 4);
    float4 bb = *(const float4*)(b + q * 4);
    float p;
    {
        float zs = fmaf(ds, as.x, bb.x), zd = fmaf(dd, ad.x, bb.x);
        p = zs * zd;
        zs = fmaf(ds, as.y, bb.y); zd = fmaf(dd, ad.y, bb.y); p = fmaf(zs, zd, p);
        zs = fmaf(ds, as.z, bb.z); zd = fmaf(dd, ad.z, bb.z); p = fmaf(zs, zd, p);
        zs = fmaf(ds, as.w, bb.w); zd = fmaf(dd, ad.w, bb.w); p = fmaf(zs, zd, p);
    }
    p += __shfl_xor_sync(0xffffffffu, p, 8);
    p += __shfl_xor_sync(0xffffffffu, p, 4);
    p += __shfl_xor_sync(0xffffffffu, p, 2);
    p += __shfl_xor_sync(0xffffffffu, p, 1);
    if (q == 0) out[edge] = p;
}

// ---------------------------------------------------------------------------
extern "C" void kernel_launch(void* const* d_in, const int* in_sizes, int n_in,
                              void* d_out, int out_size) {
    const float* x  = (const float*)d_in[0];   // [n, IN_CH]
    const int*   ei = (const int*)d_in[1];     // [2, e]
    const float* W1 = (const float*)d_in[2];
    const float* b1 = (const float*)d_in[3];
    const float* W2 = (const float*)d_in[4];
    const float* b2 = (const float*)d_in[5];
    float* out = (float*)d_out;                // [e]

    int n = in_sizes[0] / IN_CH;
    int e = in_sizes[1] / 2;
    const int* src = ei;
    const int* dst = ei + e;

    float *p_h, *p_agg1, *p_agg2;
    cudaGetSymbolAddress((void**)&p_h, g_h);
    cudaGetSymbolAddress((void**)&p_agg1, g_agg1);
    cudaGetSymbolAddress((void**)&p_agg2, g_agg2);

    const int T = 256;
    int eg = (e * 16 + T - 1) / T;             // 16 lanes per edge

    init_deg_kernel<<<(n + T - 1) / T, T>>>(n);
    degree_kernel<<<(e + T - 1) / T, T>>>(dst, e);
    dinv_kernel<<<(n + T - 1) / T, T>>>(n);

    // layer 1: h' = (X@W1)*dinv, dual-store (agg1 starts at self-loop term)
    gemm_kernel<IN_CH, false><<<(n + 127) / 128, 128>>>(x, W1, nullptr, p_h, p_agg1, n);
    agg_kernel<<<eg, T>>>(src, dst, p_h, p_agg1, e);

    // layer 2: input z1 = relu(dinv*agg1 + b1) fused into GEMM load
    gemm_kernel<HID, true><<<(n + 127) / 128, 128>>>(p_agg1, W2, b1, p_h, p_agg2, n);
    agg_kernel<<<eg, T>>>(src, dst, p_h, p_agg2, e);

    // decode with z2 = dinv*agg2 + b2 fused
    decode_kernel<<<eg, T>>>(src, dst, p_agg2, b2, out, e);
}